// round 13
// baseline (speedup 1.0000x reference)
#include <cuda_runtime.h>
#include <math.h>

#define BB 16
#define NN 128
#define HH 64
#define IT2 16         // i's per block
#define NB  (NN / IT2) // blocks per batch = 8
#define NT  1024
#define NEGS 0.01f
#define DRN2 0.16000000000000003f   // f32(0.4*0.4 in double)
#define TWO_PI 6.2831854820251465f  // 2.0 * np.float32(np.pi)

// Cross-block scratch
__device__ float g_a1[BB * NN * 2];
__device__ float g_v2[BB * NN * HH];
__device__ float g_ptw[BB * NN];
__device__ float g_part[BB * 66 * NB];
__device__ int   g_cnt1[BB];   // zero-init; reset by last block each run
__device__ int   g_cnt2[BB];

__device__ __forceinline__ float leaky(float z) {
  return fmaxf(z, 0.f) + NEGS * fminf(z, 0.f);
}

__global__ void __launch_bounds__(NT) k_fused(
    const float* __restrict__ ang, const float* __restrict__ pt,
    const float* __restrict__ W00, const float* __restrict__ b00,
    const float* __restrict__ W01, const float* __restrict__ b01,
    const float* __restrict__ W10, const float* __restrict__ b10,
    const float* __restrict__ W11, const float* __restrict__ b11,
    const float* __restrict__ Wr0, const float* __restrict__ br0,
    const float* __restrict__ Wr1, const float* __restrict__ br1,
    const float* __restrict__ Wr2, const float* __restrict__ br2,
    float* __restrict__ out) {
  int b = blockIdx.y;
  int bx = blockIdx.x;
  int t = threadIdx.x;
  int sub = t >> 6, lt = t & 63;
  int w = lt >> 5, lane = lt & 31;
  int i = bx * IT2 + sub;

  __shared__ float ax[NN], ay[NN], rr[NN];
  __shared__ unsigned msk[IT2][4];
  __shared__ float4 glist[IT2][NN];
  __shared__ float hsm[IT2][HH], fsm[IT2][HH];
  __shared__ float red[IT2][2];
  __shared__ float red4[4];
  __shared__ float big[2 * HH * HH];  // phase A: float2 (wua,wub); B: vsm
  __shared__ float w01s[65 * HH];     // staged W01 (64x65)
  __shared__ float pf[IT2][66];
  __shared__ float gg[66], gA[HH], h1[32], h2[32];
  __shared__ int isLast;

  // ===================== Phase A: layer 1 =====================
  // stage combined uv weights interleaved + W01
  {
    float2* wuv = (float2*)big;
    for (int idx = t; idx < HH * HH; idx += NT) {
      float wa = W10[idx];
      float wb = W10[HH * HH + idx];
      float wd = W10[2 * HH * HH + idx];
      wuv[idx] = make_float2(wa - wd, wb + wd);
    }
    for (int idx = t; idx < 65 * HH; idx += NT) w01s[idx] = W01[idx];
  }
  if (t < NN) {
    float2 a = ((const float2*)ang)[b * NN + t];
    ax[t] = a.x; ay[t] = a.y;
    rr[t] = sqrtf(a.x * a.x + a.y * a.y);
  }
  float pv = 0.f;
  if (bx == 0 && t < NN) {
    pv = pt[b * NN + t];
    float s = pv;
    for (int o = 16; o; o >>= 1) s += __shfl_down_sync(0xffffffffu, s, o);
    if ((t & 31) == 0) red4[t >> 5] = s;
  }
  __syncthreads();
  if (bx == 0 && t < NN) {
    float invs = 1.f / (red4[0] + red4[1] + red4[2] + red4[3]);
    g_ptw[b * NN + t] = pv * invs;
  }

  int h = lt;
  // prefetch phase-B constants BEFORE the fence flushes L1
  float wc2 = W10[192 * HH + h], ws2 = W10[193 * HH + h];
  float w11g = W11[h * 65 + 64];
  float b11g = b11[64];

  float xi = ax[i], yi = ay[i];
  float r2i = xi * xi + yi * yi;

  {
    int j0 = lt, j1 = lt + 64;
    float x0 = ax[j0], y0 = ay[j0], x1 = ax[j1], y1 = ay[j1];
    float d0x = xi - x0, d0y = yi - y0, d1x = xi - x1, d1y = yi - y1;
    bool a0 = (d0x * d0x + d0y * d0y) <= DRN2;
    bool a1 = (d1x * d1x + d1y * d1y) <= DRN2;
    unsigned m0 = __ballot_sync(0xffffffffu, a0);
    unsigned m1 = __ballot_sync(0xffffffffu, a1);
    if (lane == 0) { msk[sub][w] = m0; msk[sub][2 + w] = m1; }
    __syncthreads();
    unsigned M0 = msk[sub][0], M1 = msk[sub][1], M2 = msk[sub][2], M3 = msk[sub][3];
    int c0 = __popc(M0), c1 = __popc(M1), c2 = __popc(M2);
    unsigned below = (1u << lane) - 1u;
    if (a0) {
      int base = (w == 0) ? 0 : c0;
      int pos = base + __popc((w == 0 ? M0 : M1) & below);
      float inv = rsqrtf(r2i * (x0 * x0 + y0 * y0));
      glist[sub][pos] = make_float4((xi * x0 + yi * y0) * inv,
                                    (yi * x0 - xi * y0) * inv, rr[j0], 0.f);
    }
    if (a1) {
      int base = c0 + c1 + ((w == 0) ? 0 : c2);
      int pos = base + __popc((w == 0 ? M2 : M3) & below);
      float inv = rsqrtf(r2i * (x1 * x1 + y1 * y1));
      glist[sub][pos] = make_float4((xi * x1 + yi * y1) * inv,
                                    (yi * x1 - xi * y1) * inv, rr[j1], 0.f);
    }
  }
  __syncthreads();

  {
    unsigned M0 = msk[sub][0], M1 = msk[sub][1], M2 = msk[sub][2], M3 = msk[sub][3];
    int deg = __popc(M0) + __popc(M1) + __popc(M2) + __popc(M3);
    int degp = (deg + 3) & ~3;
    float u  = fmaf(rr[i], W00[h] - W00[128 + h], b00[h]);
    float vc = W00[64 + h] + W00[128 + h];
    float wc = W00[192 + h], ws = W00[256 + h];
    float acc0 = 0.f, acc1 = 0.f;
    for (int q = 0; q < degp; q += 4) {
      float4 ga = glist[sub][q];
      float4 gb = glist[sub][q + 1];
      float4 gc = glist[sub][q + 2];
      float4 gd = glist[sub][q + 3];
      float za = fmaf(ga.z, vc, u); za = fmaf(ga.x, wc, za); za = fmaf(ga.y, ws, za);
      float zb = fmaf(gb.z, vc, u); zb = fmaf(gb.x, wc, zb); zb = fmaf(gb.y, ws, zb);
      float zc = fmaf(gc.z, vc, u); zc = fmaf(gc.x, wc, zc); zc = fmaf(gc.y, ws, zc);
      float zd = fmaf(gd.z, vc, u); zd = fmaf(gd.x, wc, zd); zd = fmaf(gd.y, ws, zd);
      acc0 += (q     < deg) ? leaky(za) : 0.f;
      acc1 += (q + 1 < deg) ? leaky(zb) : 0.f;
      acc0 += (q + 2 < deg) ? leaky(zc) : 0.f;
      acc1 += (q + 3 < deg) ? leaky(zd) : 0.f;
    }
    hsm[sub][h] = (acc0 + acc1) * (1.f / (float)deg);
  }
  __syncthreads();

  // f1 dot (smem W01) and gamma shuffle overlap in one sync window
  {
    float d0 = b01[h], d1 = 0.f;
#pragma unroll 8
    for (int k = 0; k < HH; k += 2) {
      d0 = fmaf(hsm[sub][k], w01s[k * 65 + h], d0);
      d1 = fmaf(hsm[sub][k + 1], w01s[(k + 1) * 65 + h], d1);
    }
    fsm[sub][h] = d0 + d1;
  }
  {
    float p = hsm[sub][h] * w01s[h * 65 + 64];
    for (int o = 16; o; o >>= 1) p += __shfl_down_sync(0xffffffffu, p, o);
    if (lane == 0) red[sub][w] = p;
  }
  __syncthreads();

  if (lt == 0) {
    float gam = red[sub][0] + red[sub][1] + b01[64];
    float a2 = TWO_PI * gam;
    float co = cosf(a2), si = sinf(a2);
    g_a1[(b * NN + i) * 2 + 0] = co * xi - si * yi;
    g_a1[(b * NN + i) * 2 + 1] = si * xi + co * yi;
  }

  // u2 (register) and v2 (global) via interleaved wuv, 4 FMA chains
  float ureg;
  {
    const float2* wuv = (const float2*)big;
    float u0 = b10[h], u1 = 0.f, v0 = 0.f, v1 = 0.f;
#pragma unroll 8
    for (int d = 0; d < HH; d += 2) {
      float f0 = fsm[sub][d];
      float f1v = fsm[sub][d + 1];
      float2 w0 = wuv[d * HH + h];
      float2 w1 = wuv[(d + 1) * HH + h];
      u0 = fmaf(f0, w0.x, u0);
      v0 = fmaf(f0, w0.y, v0);
      u1 = fmaf(f1v, w1.x, u1);
      v1 = fmaf(f1v, w1.y, v1);
    }
    ureg = u0 + u1;
    g_v2[(b * NN + i) * HH + h] = v0 + v1;
  }

  // ===================== Batch barrier =====================
  __syncthreads();
  __threadfence();
  if (t == 0) {
    atomicAdd(&g_cnt1[b], 1);
    while (atomicAdd(&g_cnt1[b], 0) < NB) __nanosleep(32);
  }
  __syncthreads();

  // ===================== Phase B: layer 2 =====================
  if (t < NN) {
    float2 a = ((const float2*)g_a1)[b * NN + t];
    ax[t] = a.x; ay[t] = a.y;
  }
  {
    const float4* vsrc = (const float4*)(g_v2 + (size_t)b * NN * HH);
#pragma unroll
    for (int idx = t; idx < NN * HH / 4; idx += NT)
      ((float4*)big)[idx] = vsrc[idx];
  }
  __syncthreads();

  xi = ax[i]; yi = ay[i];
  r2i = xi * xi + yi * yi;

  {
    int j0 = lt, j1 = lt + 64;
    float x0 = ax[j0], y0 = ay[j0], x1 = ax[j1], y1 = ay[j1];
    float d0x = xi - x0, d0y = yi - y0, d1x = xi - x1, d1y = yi - y1;
    bool a0 = (d0x * d0x + d0y * d0y) <= DRN2;
    bool a1 = (d1x * d1x + d1y * d1y) <= DRN2;
    unsigned m0 = __ballot_sync(0xffffffffu, a0);
    unsigned m1 = __ballot_sync(0xffffffffu, a1);
    if (lane == 0) { msk[sub][w] = m0; msk[sub][2 + w] = m1; }
    __syncthreads();
    unsigned M0 = msk[sub][0], M1 = msk[sub][1], M2 = msk[sub][2], M3 = msk[sub][3];
    int c0 = __popc(M0), c1 = __popc(M1), c2 = __popc(M2);
    unsigned below = (1u << lane) - 1u;
    if (a0) {
      int base = (w == 0) ? 0 : c0;
      int pos = base + __popc((w == 0 ? M0 : M1) & below);
      float inv = rsqrtf(r2i * (x0 * x0 + y0 * y0));
      glist[sub][pos] = make_float4((xi * x0 + yi * y0) * inv,
                                    (yi * x0 - xi * y0) * inv,
                                    __int_as_float(j0 * HH), 0.f);
    }
    if (a1) {
      int base = c0 + c1 + ((w == 0) ? 0 : c2);
      int pos = base + __popc((w == 0 ? M2 : M3) & below);
      float inv = rsqrtf(r2i * (x1 * x1 + y1 * y1));
      glist[sub][pos] = make_float4((xi * x1 + yi * y1) * inv,
                                    (yi * x1 - xi * y1) * inv,
                                    __int_as_float(j1 * HH), 0.f);
    }
  }
  __syncthreads();

  {
    unsigned M0 = msk[sub][0], M1 = msk[sub][1], M2 = msk[sub][2], M3 = msk[sub][3];
    int deg = __popc(M0) + __popc(M1) + __popc(M2) + __popc(M3);
    int degp = (deg + 3) & ~3;
    float acc0 = 0.f, acc1 = 0.f;
    for (int q = 0; q < degp; q += 4) {
      float4 ga = glist[sub][q];
      float4 gb = glist[sub][q + 1];
      float4 gc = glist[sub][q + 2];
      float4 gd = glist[sub][q + 3];
      // guard indices: stale entries beyond deg hold non-index bits
      int ia = (q     < deg) ? __float_as_int(ga.z) : 0;
      int ib = (q + 1 < deg) ? __float_as_int(gb.z) : 0;
      int ic = (q + 2 < deg) ? __float_as_int(gc.z) : 0;
      int id = (q + 3 < deg) ? __float_as_int(gd.z) : 0;
      float va = big[ia + h], vb = big[ib + h], vc4 = big[ic + h], vd = big[id + h];
      float za = ureg + va; za = fmaf(ga.x, wc2, za); za = fmaf(ga.y, ws2, za);
      float zb = ureg + vb; zb = fmaf(gb.x, wc2, zb); zb = fmaf(gb.y, ws2, zb);
      float zc = ureg + vc4; zc = fmaf(gc.x, wc2, zc); zc = fmaf(gc.y, ws2, zc);
      float zd = ureg + vd; zd = fmaf(gd.x, wc2, zd); zd = fmaf(gd.y, ws2, zd);
      acc0 += (q     < deg) ? leaky(za) : 0.f;
      acc1 += (q + 1 < deg) ? leaky(zb) : 0.f;
      acc0 += (q + 2 < deg) ? leaky(zc) : 0.f;
      acc1 += (q + 3 < deg) ? leaky(zd) : 0.f;
    }
    hsm[sub][h] = (acc0 + acc1) * (1.f / (float)deg);
  }

  {
    float p = hsm[sub][h] * w11g;
    for (int o = 16; o; o >>= 1) p += __shfl_down_sync(0xffffffffu, p, o);
    if (lane == 0) red[sub][w] = p;
  }
  __syncthreads();

  // partials: S = sum_i ptw_i * hs2_i (W11 applied once in phase C)
  float pw = g_ptw[b * NN + i];
  pf[sub][h] = pw * hsm[sub][h];
  if (lt == 0) {
    float gam = red[sub][0] + red[sub][1] + b11g;
    float a2 = TWO_PI * gam;
    float co = cosf(a2), si = sinf(a2);
    pf[sub][64] = pw * (co * xi - si * yi);
    pf[sub][65] = pw * (si * xi + co * yi);
  }
  __syncthreads();

  if (t < 66) {
    float s = pf[0][t];
#pragma unroll
    for (int q = 1; q < IT2; ++q) s += pf[q][t];
    g_part[((size_t)b * 66 + t) * NB + bx] = s;
  }

  // ===================== Phase C: last block readout =====================
  __threadfence();
  if (t == 0) isLast = (atomicAdd(&g_cnt2[b], 1) == NB - 1);
  __syncthreads();
  if (!isLast) return;

  {
    int wid = t >> 5;  // 32 warps
    const float* part = g_part + (size_t)b * 66 * NB;
    for (int c = wid; c < 66; c += 32) {
      float v = (lane < NB) ? part[c * NB + lane] : 0.f;
#pragma unroll
      for (int o = 4; o; o >>= 1) v += __shfl_down_sync(0xffffffffu, v, o);
      if (lane == 0) gg[c] = v;
    }
    __syncthreads();

    // apply W11 once: gA = S @ W11[:, :64] + b11 (Σptw = 1)
    if (t < HH) {
      float z = b11[t];
#pragma unroll 8
      for (int k = 0; k < HH; ++k) z = fmaf(gg[k], W11[k * 65 + t], z);
      gA[t] = z;
    }
    __syncthreads();

    if (t < 32) {
      float z = br0[t];
#pragma unroll 8
      for (int d = 0; d < 64; ++d) z = fmaf(gA[d], Wr0[d * 32 + t], z);
      h1[t] = leaky(z);
    }
    __syncthreads();
    if (t < 32) {
      float z = br1[t];
#pragma unroll 8
      for (int d = 0; d < 32; ++d) z = fmaf(h1[d], Wr1[d * 32 + t], z);
      h2[t] = leaky(z);
    }
    __syncthreads();
    if (t == 0) {
      float z = br2[0];
#pragma unroll 8
      for (int d = 0; d < 32; ++d) z = fmaf(h2[d], Wr2[d], z);
      out[b * 3 + 0] = 1.f / (1.f + expf(-z));
      out[b * 3 + 1] = gg[64];
      out[b * 3 + 2] = gg[65];
      g_cnt1[b] = 0;   // reset for next graph replay
      g_cnt2[b] = 0;
    }
  }
}

extern "C" void kernel_launch(void* const* d_in, const int* in_sizes, int n_in,
                              void* d_out, int out_size) {
  const float* pt  = (const float*)d_in[0];
  const float* ang = (const float*)d_in[1];
  const float* W00 = (const float*)d_in[2];
  const float* b00 = (const float*)d_in[3];
  const float* W01 = (const float*)d_in[4];
  const float* b01 = (const float*)d_in[5];
  const float* W10 = (const float*)d_in[6];
  const float* b10 = (const float*)d_in[7];
  const float* W11 = (const float*)d_in[8];
  const float* b11 = (const float*)d_in[9];
  const float* Wr0 = (const float*)d_in[10];
  const float* br0 = (const float*)d_in[11];
  const float* Wr1 = (const float*)d_in[12];
  const float* br1 = (const float*)d_in[13];
  const float* Wr2 = (const float*)d_in[14];
  const float* br2 = (const float*)d_in[15];
  float* out = (float*)d_out;

  k_fused<<<dim3(NB, BB), NT>>>(ang, pt, W00, b00, W01, b01, W10, b10,
                                W11, b11, Wr0, br0, Wr1, br1, Wr2, br2, out);
}

// round 14
// speedup vs baseline: 1.0013x; 1.0013x over previous
#include <cuda_runtime.h>
#include <math.h>

#define BB 16
#define NN 128
#define HH 64
#define IT2 16         // i's per block
#define NB  (NN / IT2) // blocks per batch = 8
#define NT  1024
#define NEGS 0.01f
#define DRN2 0.16000000000000003f   // f32(0.4*0.4 in double)
#define TWO_PI 6.2831854820251465f  // 2.0 * np.float32(np.pi)

// Cross-block scratch
__device__ float g_a1[BB * NN * 2];
__device__ float g_v2[BB * NN * HH];
__device__ float g_ptw[BB * NN];
__device__ float g_part[BB * 66 * NB];
__device__ int   g_cnt1[BB];   // zero-init; reset by last block each run
__device__ int   g_cnt2[BB];

__device__ __forceinline__ float leaky(float z) {
  return fmaxf(z, 0.f) + NEGS * fminf(z, 0.f);
}

__global__ void __launch_bounds__(NT) k_fused(
    const float* __restrict__ ang, const float* __restrict__ pt,
    const float* __restrict__ W00, const float* __restrict__ b00,
    const float* __restrict__ W01, const float* __restrict__ b01,
    const float* __restrict__ W10, const float* __restrict__ b10,
    const float* __restrict__ W11, const float* __restrict__ b11,
    const float* __restrict__ Wr0, const float* __restrict__ br0,
    const float* __restrict__ Wr1, const float* __restrict__ br1,
    const float* __restrict__ Wr2, const float* __restrict__ br2,
    float* __restrict__ out) {
  int b = blockIdx.y;
  int bx = blockIdx.x;
  int t = threadIdx.x;
  int sub = t >> 6, lt = t & 63;
  int w = lt >> 5, lane = lt & 31;
  int i = bx * IT2 + sub;

  __shared__ float ax[NN], ay[NN], rr[NN];
  __shared__ unsigned msk[IT2][4];
  __shared__ float4 glist[IT2][NN];
  __shared__ float hsm[IT2][HH], fsm[IT2][HH];
  __shared__ float red[IT2][2];
  __shared__ float red4[4];
  __shared__ float big[2 * HH * HH];  // phase A: float2 (wua,wub); B: vsm
  __shared__ float pf[IT2][66];
  __shared__ float gg[66], gA[HH], h1[32], h2[32];
  __shared__ int isLast;

  // ===================== Phase A: layer 1 =====================
  // stage combined uv weights interleaved: wuv[d*HH+h] = (W10a-W10d, W10b+W10d)
  {
    float2* wuv = (float2*)big;
    for (int idx = t; idx < HH * HH; idx += NT) {
      float wa = W10[idx];
      float wb = W10[HH * HH + idx];
      float wd = W10[2 * HH * HH + idx];
      wuv[idx] = make_float2(wa - wd, wb + wd);
    }
  }
  if (t < NN) {
    float2 a = ((const float2*)ang)[b * NN + t];
    ax[t] = a.x; ay[t] = a.y;
    rr[t] = sqrtf(a.x * a.x + a.y * a.y);
  }
  float pv = 0.f;
  if (bx == 0 && t < NN) {
    pv = pt[b * NN + t];
    float s = pv;
    for (int o = 16; o; o >>= 1) s += __shfl_down_sync(0xffffffffu, s, o);
    if ((t & 31) == 0) red4[t >> 5] = s;
  }
  __syncthreads();
  if (bx == 0 && t < NN) {
    float invs = 1.f / (red4[0] + red4[1] + red4[2] + red4[3]);
    g_ptw[b * NN + t] = pv * invs;
  }

  int h = lt;
  // prefetch phase-B constants BEFORE the fence flushes L1
  float wc2 = W10[192 * HH + h], ws2 = W10[193 * HH + h];
  float w11g = W11[h * 65 + 64];
  float b11g = b11[64];

  float xi = ax[i], yi = ay[i];
  float r2i = xi * xi + yi * yi;

  {
    int j0 = lt, j1 = lt + 64;
    float x0 = ax[j0], y0 = ay[j0], x1 = ax[j1], y1 = ay[j1];
    float d0x = xi - x0, d0y = yi - y0, d1x = xi - x1, d1y = yi - y1;
    bool a0 = (d0x * d0x + d0y * d0y) <= DRN2;
    bool a1 = (d1x * d1x + d1y * d1y) <= DRN2;
    unsigned m0 = __ballot_sync(0xffffffffu, a0);
    unsigned m1 = __ballot_sync(0xffffffffu, a1);
    if (lane == 0) { msk[sub][w] = m0; msk[sub][2 + w] = m1; }
    __syncthreads();
    unsigned M0 = msk[sub][0], M1 = msk[sub][1], M2 = msk[sub][2], M3 = msk[sub][3];
    int c0 = __popc(M0), c1 = __popc(M1), c2 = __popc(M2);
    unsigned below = (1u << lane) - 1u;
    if (a0) {
      int base = (w == 0) ? 0 : c0;
      int pos = base + __popc((w == 0 ? M0 : M1) & below);
      float inv = rsqrtf(r2i * (x0 * x0 + y0 * y0));
      glist[sub][pos] = make_float4((xi * x0 + yi * y0) * inv,
                                    (yi * x0 - xi * y0) * inv, rr[j0], 0.f);
    }
    if (a1) {
      int base = c0 + c1 + ((w == 0) ? 0 : c2);
      int pos = base + __popc((w == 0 ? M2 : M3) & below);
      float inv = rsqrtf(r2i * (x1 * x1 + y1 * y1));
      glist[sub][pos] = make_float4((xi * x1 + yi * y1) * inv,
                                    (yi * x1 - xi * y1) * inv, rr[j1], 0.f);
    }
  }
  __syncthreads();

  {
    unsigned M0 = msk[sub][0], M1 = msk[sub][1], M2 = msk[sub][2], M3 = msk[sub][3];
    int deg = __popc(M0) + __popc(M1) + __popc(M2) + __popc(M3);
    int degp = (deg + 1) & ~1;
    float u  = fmaf(rr[i], W00[h] - W00[128 + h], b00[h]);
    float vc = W00[64 + h] + W00[128 + h];
    float wc = W00[192 + h], ws = W00[256 + h];
    float acc0 = 0.f, acc1 = 0.f;
    for (int q = 0; q < degp; q += 2) {
      float4 ga = glist[sub][q];
      float4 gb = glist[sub][q + 1];
      float za = fmaf(ga.z, vc, u); za = fmaf(ga.x, wc, za); za = fmaf(ga.y, ws, za);
      float zb = fmaf(gb.z, vc, u); zb = fmaf(gb.x, wc, zb); zb = fmaf(gb.y, ws, zb);
      acc0 += leaky(za);
      acc1 += (q + 1 < deg) ? leaky(zb) : 0.f;
    }
    hsm[sub][h] = (acc0 + acc1) * (1.f / (float)deg);
  }
  __syncthreads();

  // f1 dot and gamma shuffle overlap in one sync window
  {
    float d0 = b01[h], d1 = 0.f;
#pragma unroll 8
    for (int k = 0; k < HH; k += 2) {
      d0 = fmaf(hsm[sub][k], W01[k * 65 + h], d0);
      d1 = fmaf(hsm[sub][k + 1], W01[(k + 1) * 65 + h], d1);
    }
    fsm[sub][h] = d0 + d1;
  }
  {
    float p = hsm[sub][h] * W01[h * 65 + 64];
    for (int o = 16; o; o >>= 1) p += __shfl_down_sync(0xffffffffu, p, o);
    if (lane == 0) red[sub][w] = p;
  }
  __syncthreads();

  if (lt == 0) {
    float gam = red[sub][0] + red[sub][1] + b01[64];
    float a2 = TWO_PI * gam;
    float co = cosf(a2), si = sinf(a2);
    g_a1[(b * NN + i) * 2 + 0] = co * xi - si * yi;
    g_a1[(b * NN + i) * 2 + 1] = si * xi + co * yi;
  }

  // u2 (register) and v2 (global) via interleaved wuv, 4 FMA chains
  float ureg;
  {
    const float2* wuv = (const float2*)big;
    float u0 = b10[h], u1 = 0.f, v0 = 0.f, v1 = 0.f;
#pragma unroll 8
    for (int d = 0; d < HH; d += 2) {
      float f0 = fsm[sub][d];
      float f1v = fsm[sub][d + 1];
      float2 w0 = wuv[d * HH + h];
      float2 w1 = wuv[(d + 1) * HH + h];
      u0 = fmaf(f0, w0.x, u0);
      v0 = fmaf(f0, w0.y, v0);
      u1 = fmaf(f1v, w1.x, u1);
      v1 = fmaf(f1v, w1.y, v1);
    }
    ureg = u0 + u1;
    g_v2[(b * NN + i) * HH + h] = v0 + v1;
  }

  // ===================== Batch barrier =====================
  __syncthreads();
  __threadfence();
  if (t == 0) {
    atomicAdd(&g_cnt1[b], 1);
    while (atomicAdd(&g_cnt1[b], 0) < NB) __nanosleep(32);
  }
  __syncthreads();

  // ===================== Phase B: layer 2 =====================
  if (t < NN) {
    float2 a = ((const float2*)g_a1)[b * NN + t];
    ax[t] = a.x; ay[t] = a.y;
  }
  {
    const float4* vsrc = (const float4*)(g_v2 + (size_t)b * NN * HH);
#pragma unroll
    for (int idx = t; idx < NN * HH / 4; idx += NT)
      ((float4*)big)[idx] = vsrc[idx];
  }
  __syncthreads();

  xi = ax[i]; yi = ay[i];
  r2i = xi * xi + yi * yi;

  {
    int j0 = lt, j1 = lt + 64;
    float x0 = ax[j0], y0 = ay[j0], x1 = ax[j1], y1 = ay[j1];
    float d0x = xi - x0, d0y = yi - y0, d1x = xi - x1, d1y = yi - y1;
    bool a0 = (d0x * d0x + d0y * d0y) <= DRN2;
    bool a1 = (d1x * d1x + d1y * d1y) <= DRN2;
    unsigned m0 = __ballot_sync(0xffffffffu, a0);
    unsigned m1 = __ballot_sync(0xffffffffu, a1);
    if (lane == 0) { msk[sub][w] = m0; msk[sub][2 + w] = m1; }
    __syncthreads();
    unsigned M0 = msk[sub][0], M1 = msk[sub][1], M2 = msk[sub][2], M3 = msk[sub][3];
    int c0 = __popc(M0), c1 = __popc(M1), c2 = __popc(M2);
    unsigned below = (1u << lane) - 1u;
    if (a0) {
      int base = (w == 0) ? 0 : c0;
      int pos = base + __popc((w == 0 ? M0 : M1) & below);
      float inv = rsqrtf(r2i * (x0 * x0 + y0 * y0));
      glist[sub][pos] = make_float4((xi * x0 + yi * y0) * inv,
                                    (yi * x0 - xi * y0) * inv,
                                    __int_as_float(j0 * HH), 0.f);
    }
    if (a1) {
      int base = c0 + c1 + ((w == 0) ? 0 : c2);
      int pos = base + __popc((w == 0 ? M2 : M3) & below);
      float inv = rsqrtf(r2i * (x1 * x1 + y1 * y1));
      glist[sub][pos] = make_float4((xi * x1 + yi * y1) * inv,
                                    (yi * x1 - xi * y1) * inv,
                                    __int_as_float(j1 * HH), 0.f);
    }
  }
  __syncthreads();

  {
    unsigned M0 = msk[sub][0], M1 = msk[sub][1], M2 = msk[sub][2], M3 = msk[sub][3];
    int deg = __popc(M0) + __popc(M1) + __popc(M2) + __popc(M3);
    int degp = (deg + 1) & ~1;
    float acc0 = 0.f, acc1 = 0.f;
    for (int q = 0; q < degp; q += 2) {
      float4 ga = glist[sub][q];
      float4 gb = glist[sub][q + 1];
      int ia = __float_as_int(ga.z);
      int ib = (q + 1 < deg) ? __float_as_int(gb.z) : 0;  // guard stale index
      float va = big[ia + h];
      float vb = big[ib + h];
      float za = ureg + va; za = fmaf(ga.x, wc2, za); za = fmaf(ga.y, ws2, za);
      float zb = ureg + vb; zb = fmaf(gb.x, wc2, zb); zb = fmaf(gb.y, ws2, zb);
      acc0 += leaky(za);
      acc1 += (q + 1 < deg) ? leaky(zb) : 0.f;
    }
    hsm[sub][h] = (acc0 + acc1) * (1.f / (float)deg);
  }

  {
    float p = hsm[sub][h] * w11g;
    for (int o = 16; o; o >>= 1) p += __shfl_down_sync(0xffffffffu, p, o);
    if (lane == 0) red[sub][w] = p;
  }
  __syncthreads();

  // partials: S = sum_i ptw_i * hs2_i (W11 applied once in phase C)
  float pw = g_ptw[b * NN + i];
  pf[sub][h] = pw * hsm[sub][h];
  if (lt == 0) {
    float gam = red[sub][0] + red[sub][1] + b11g;
    float a2 = TWO_PI * gam;
    float co = cosf(a2), si = sinf(a2);
    pf[sub][64] = pw * (co * xi - si * yi);
    pf[sub][65] = pw * (si * xi + co * yi);
  }
  __syncthreads();

  if (t < 66) {
    float s = pf[0][t];
#pragma unroll
    for (int q = 1; q < IT2; ++q) s += pf[q][t];
    g_part[((size_t)b * 66 + t) * NB + bx] = s;
  }

  // ===================== Phase C: last block readout =====================
  __threadfence();
  if (t == 0) isLast = (atomicAdd(&g_cnt2[b], 1) == NB - 1);
  __syncthreads();
  if (!isLast) return;

  {
    int wid = t >> 5;  // 32 warps
    const float* part = g_part + (size_t)b * 66 * NB;
    for (int c = wid; c < 66; c += 32) {
      float v = (lane < NB) ? part[c * NB + lane] : 0.f;
#pragma unroll
      for (int o = 4; o; o >>= 1) v += __shfl_down_sync(0xffffffffu, v, o);
      if (lane == 0) gg[c] = v;
    }
    __syncthreads();

    // apply W11 once: gA = S @ W11[:, :64] + b11 (Σptw = 1)
    if (t < HH) {
      float z = b11[t];
#pragma unroll 8
      for (int k = 0; k < HH; ++k) z = fmaf(gg[k], W11[k * 65 + t], z);
      gA[t] = z;
    }
    __syncthreads();

    if (t < 32) {
      float z = br0[t];
#pragma unroll 8
      for (int d = 0; d < 64; ++d) z = fmaf(gA[d], Wr0[d * 32 + t], z);
      h1[t] = leaky(z);
    }
    __syncthreads();
    if (t < 32) {
      float z = br1[t];
#pragma unroll 8
      for (int d = 0; d < 32; ++d) z = fmaf(h1[d], Wr1[d * 32 + t], z);
      h2[t] = leaky(z);
    }
    __syncthreads();
    if (t == 0) {
      float z = br2[0];
#pragma unroll 8
      for (int d = 0; d < 32; ++d) z = fmaf(h2[d], Wr2[d], z);
      out[b * 3 + 0] = 1.f / (1.f + expf(-z));
      out[b * 3 + 1] = gg[64];
      out[b * 3 + 2] = gg[65];
      g_cnt1[b] = 0;   // reset for next graph replay
      g_cnt2[b] = 0;
    }
  }
}

extern "C" void kernel_launch(void* const* d_in, const int* in_sizes, int n_in,
                              void* d_out, int out_size) {
  const float* pt  = (const float*)d_in[0];
  const float* ang = (const float*)d_in[1];
  const float* W00 = (const float*)d_in[2];
  const float* b00 = (const float*)d_in[3];
  const float* W01 = (const float*)d_in[4];
  const float* b01 = (const float*)d_in[5];
  const float* W10 = (const float*)d_in[6];
  const float* b10 = (const float*)d_in[7];
  const float* W11 = (const float*)d_in[8];
  const float* b11 = (const float*)d_in[9];
  const float* Wr0 = (const float*)d_in[10];
  const float* br0 = (const float*)d_in[11];
  const float* Wr1 = (const float*)d_in[12];
  const float* br1 = (const float*)d_in[13];
  const float* Wr2 = (const float*)d_in[14];
  const float* br2 = (const float*)d_in[15];
  float* out = (float*)d_out;

  k_fused<<<dim3(NB, BB), NT>>>(ang, pt, W00, b00, W01, b01, W10, b10,
                                W11, b11, Wr0, br0, Wr1, br1, Wr2, br2, out);
}

// round 15
// speedup vs baseline: 1.0115x; 1.0102x over previous
#include <cuda_runtime.h>
#include <math.h>

#define BB 16
#define NN 128
#define HH 64
#define IT2 16         // i's per block
#define NB  (NN / IT2) // blocks per batch = 8
#define NT  1024
#define NEGS 0.01f
#define DRN2 0.16000000000000003f   // f32(0.4*0.4 in double)
#define TWO_PI 6.2831854820251465f  // 2.0 * np.float32(np.pi)

// Cross-block scratch
__device__ float g_a1[BB * NN * 2];
__device__ float g_v2[BB * NN * HH];
__device__ float g_ptw[BB * NN];
__device__ float g_part[BB * 66 * NB];
__device__ int   g_cnt1[BB];   // zero-init; reset by last block each run
__device__ int   g_cnt2[BB];

__device__ __forceinline__ float leaky(float z) {
  return fmaxf(z, 0.f) + NEGS * fminf(z, 0.f);
}

__global__ void __launch_bounds__(NT) k_fused(
    const float* __restrict__ ang, const float* __restrict__ pt,
    const float* __restrict__ W00, const float* __restrict__ b00,
    const float* __restrict__ W01, const float* __restrict__ b01,
    const float* __restrict__ W10, const float* __restrict__ b10,
    const float* __restrict__ W11, const float* __restrict__ b11,
    const float* __restrict__ Wr0, const float* __restrict__ br0,
    const float* __restrict__ Wr1, const float* __restrict__ br1,
    const float* __restrict__ Wr2, const float* __restrict__ br2,
    float* __restrict__ out) {
  int b = blockIdx.y;
  int bx = blockIdx.x;
  int t = threadIdx.x;
  int sub = t >> 6, lt = t & 63;
  int w = lt >> 5, lane = lt & 31;
  int i = bx * IT2 + sub;

  __shared__ float ax[NN], ay[NN], rr[NN];
  __shared__ unsigned msk[IT2][4];
  __shared__ float4 glist[IT2][NN];
  __shared__ float hsm[IT2][HH], fsm[IT2][HH];
  __shared__ float red[IT2][2];
  __shared__ float red4[4];
  __shared__ float big[2 * HH * HH];  // phase A: float2 (wua,wub); B: vsm
  __shared__ float w01s[65 * HH];     // staged W01 (L1 is flushed per launch)
  __shared__ float pf[IT2][66];
  __shared__ float gg[66], gA[HH], h1[32], h2[32];
  __shared__ int isLast;

  // ===================== Phase A: layer 1 =====================
  // stage combined uv weights interleaved + W01
  {
    float2* wuv = (float2*)big;
    for (int idx = t; idx < HH * HH; idx += NT) {
      float wa = W10[idx];
      float wb = W10[HH * HH + idx];
      float wd = W10[2 * HH * HH + idx];
      wuv[idx] = make_float2(wa - wd, wb + wd);
    }
    for (int idx = t; idx < 65 * HH; idx += NT) w01s[idx] = W01[idx];
  }
  if (t < NN) {
    float2 a = ((const float2*)ang)[b * NN + t];
    ax[t] = a.x; ay[t] = a.y;
    rr[t] = sqrtf(a.x * a.x + a.y * a.y);
  }
  float pv = 0.f;
  if (bx == 0 && t < NN) {
    pv = pt[b * NN + t];
    float s = pv;
    for (int o = 16; o; o >>= 1) s += __shfl_down_sync(0xffffffffu, s, o);
    if ((t & 31) == 0) red4[t >> 5] = s;
  }
  __syncthreads();
  if (bx == 0 && t < NN) {
    float invs = 1.f / (red4[0] + red4[1] + red4[2] + red4[3]);
    g_ptw[b * NN + t] = pv * invs;
  }

  int h = lt;
  // prefetch phase-B constants BEFORE the fence flushes L1
  float wc2 = W10[192 * HH + h], ws2 = W10[193 * HH + h];
  float w11g = W11[h * 65 + 64];
  float b11g = b11[64];

  float xi = ax[i], yi = ay[i];
  float r2i = xi * xi + yi * yi;

  {
    int j0 = lt, j1 = lt + 64;
    float x0 = ax[j0], y0 = ay[j0], x1 = ax[j1], y1 = ay[j1];
    float d0x = xi - x0, d0y = yi - y0, d1x = xi - x1, d1y = yi - y1;
    bool a0 = (d0x * d0x + d0y * d0y) <= DRN2;
    bool a1 = (d1x * d1x + d1y * d1y) <= DRN2;
    unsigned m0 = __ballot_sync(0xffffffffu, a0);
    unsigned m1 = __ballot_sync(0xffffffffu, a1);
    if (lane == 0) { msk[sub][w] = m0; msk[sub][2 + w] = m1; }
    __syncthreads();
    unsigned M0 = msk[sub][0], M1 = msk[sub][1], M2 = msk[sub][2], M3 = msk[sub][3];
    int c0 = __popc(M0), c1 = __popc(M1), c2 = __popc(M2);
    unsigned below = (1u << lane) - 1u;
    if (a0) {
      int base = (w == 0) ? 0 : c0;
      int pos = base + __popc((w == 0 ? M0 : M1) & below);
      float inv = rsqrtf(r2i * (x0 * x0 + y0 * y0));
      glist[sub][pos] = make_float4((xi * x0 + yi * y0) * inv,
                                    (yi * x0 - xi * y0) * inv, rr[j0], 0.f);
    }
    if (a1) {
      int base = c0 + c1 + ((w == 0) ? 0 : c2);
      int pos = base + __popc((w == 0 ? M2 : M3) & below);
      float inv = rsqrtf(r2i * (x1 * x1 + y1 * y1));
      glist[sub][pos] = make_float4((xi * x1 + yi * y1) * inv,
                                    (yi * x1 - xi * y1) * inv, rr[j1], 0.f);
    }
  }
  __syncthreads();

  {
    unsigned M0 = msk[sub][0], M1 = msk[sub][1], M2 = msk[sub][2], M3 = msk[sub][3];
    int deg = __popc(M0) + __popc(M1) + __popc(M2) + __popc(M3);
    float u  = fmaf(rr[i], W00[h] - W00[128 + h], b00[h]);
    float vc = W00[64 + h] + W00[128 + h];
    float wc = W00[192 + h], ws = W00[256 + h];
    float acc = 0.f;
    for (int q = 0; q < deg; ++q) {
      float4 g4 = glist[sub][q];
      float z = fmaf(g4.z, vc, u);
      z = fmaf(g4.x, wc, z);
      z = fmaf(g4.y, ws, z);
      acc += leaky(z);
    }
    hsm[sub][h] = acc * (1.f / (float)deg);
  }
  __syncthreads();

  // f1 dot (smem W01) and gamma shuffle overlap in one sync window
  {
    float d0 = b01[h], d1 = 0.f;
#pragma unroll 8
    for (int k = 0; k < HH; k += 2) {
      d0 = fmaf(hsm[sub][k], w01s[k * 65 + h], d0);
      d1 = fmaf(hsm[sub][k + 1], w01s[(k + 1) * 65 + h], d1);
    }
    fsm[sub][h] = d0 + d1;
  }
  {
    float p = hsm[sub][h] * w01s[h * 65 + 64];
    for (int o = 16; o; o >>= 1) p += __shfl_down_sync(0xffffffffu, p, o);
    if (lane == 0) red[sub][w] = p;
  }
  __syncthreads();

  if (lt == 0) {
    float gam = red[sub][0] + red[sub][1] + b01[64];
    float a2 = TWO_PI * gam;
    float co = cosf(a2), si = sinf(a2);
    g_a1[(b * NN + i) * 2 + 0] = co * xi - si * yi;
    g_a1[(b * NN + i) * 2 + 1] = si * xi + co * yi;
  }

  // u2 (register) and v2 (global) via interleaved wuv, 4 FMA chains
  float ureg;
  {
    const float2* wuv = (const float2*)big;
    float u0 = b10[h], u1 = 0.f, v0 = 0.f, v1 = 0.f;
#pragma unroll 8
    for (int d = 0; d < HH; d += 2) {
      float f0 = fsm[sub][d];
      float f1v = fsm[sub][d + 1];
      float2 w0 = wuv[d * HH + h];
      float2 w1 = wuv[(d + 1) * HH + h];
      u0 = fmaf(f0, w0.x, u0);
      v0 = fmaf(f0, w0.y, v0);
      u1 = fmaf(f1v, w1.x, u1);
      v1 = fmaf(f1v, w1.y, v1);
    }
    ureg = u0 + u1;
    g_v2[(b * NN + i) * HH + h] = v0 + v1;
  }

  // ===================== Batch barrier =====================
  __syncthreads();
  __threadfence();
  if (t == 0) {
    atomicAdd(&g_cnt1[b], 1);
    while (atomicAdd(&g_cnt1[b], 0) < NB) __nanosleep(32);
  }
  __syncthreads();

  // ===================== Phase B: layer 2 =====================
  if (t < NN) {
    float2 a = ((const float2*)g_a1)[b * NN + t];
    ax[t] = a.x; ay[t] = a.y;
  }
  {
    const float4* vsrc = (const float4*)(g_v2 + (size_t)b * NN * HH);
#pragma unroll
    for (int idx = t; idx < NN * HH / 4; idx += NT)
      ((float4*)big)[idx] = vsrc[idx];
  }
  __syncthreads();

  xi = ax[i]; yi = ay[i];
  r2i = xi * xi + yi * yi;

  {
    int j0 = lt, j1 = lt + 64;
    float x0 = ax[j0], y0 = ay[j0], x1 = ax[j1], y1 = ay[j1];
    float d0x = xi - x0, d0y = yi - y0, d1x = xi - x1, d1y = yi - y1;
    bool a0 = (d0x * d0x + d0y * d0y) <= DRN2;
    bool a1 = (d1x * d1x + d1y * d1y) <= DRN2;
    unsigned m0 = __ballot_sync(0xffffffffu, a0);
    unsigned m1 = __ballot_sync(0xffffffffu, a1);
    if (lane == 0) { msk[sub][w] = m0; msk[sub][2 + w] = m1; }
    __syncthreads();
    unsigned M0 = msk[sub][0], M1 = msk[sub][1], M2 = msk[sub][2], M3 = msk[sub][3];
    int c0 = __popc(M0), c1 = __popc(M1), c2 = __popc(M2);
    unsigned below = (1u << lane) - 1u;
    if (a0) {
      int base = (w == 0) ? 0 : c0;
      int pos = base + __popc((w == 0 ? M0 : M1) & below);
      float inv = rsqrtf(r2i * (x0 * x0 + y0 * y0));
      glist[sub][pos] = make_float4((xi * x0 + yi * y0) * inv,
                                    (yi * x0 - xi * y0) * inv,
                                    __int_as_float(j0 * HH), 0.f);
    }
    if (a1) {
      int base = c0 + c1 + ((w == 0) ? 0 : c2);
      int pos = base + __popc((w == 0 ? M2 : M3) & below);
      float inv = rsqrtf(r2i * (x1 * x1 + y1 * y1));
      glist[sub][pos] = make_float4((xi * x1 + yi * y1) * inv,
                                    (yi * x1 - xi * y1) * inv,
                                    __int_as_float(j1 * HH), 0.f);
    }
  }
  __syncthreads();

  {
    unsigned M0 = msk[sub][0], M1 = msk[sub][1], M2 = msk[sub][2], M3 = msk[sub][3];
    int deg = __popc(M0) + __popc(M1) + __popc(M2) + __popc(M3);
    float acc = 0.f;
    for (int q = 0; q < deg; ++q) {
      float4 g4 = glist[sub][q];
      float z = ureg + big[__float_as_int(g4.z) + h];
      z = fmaf(g4.x, wc2, z);
      z = fmaf(g4.y, ws2, z);
      acc += leaky(z);
    }
    hsm[sub][h] = acc * (1.f / (float)deg);
  }

  {
    float p = hsm[sub][h] * w11g;
    for (int o = 16; o; o >>= 1) p += __shfl_down_sync(0xffffffffu, p, o);
    if (lane == 0) red[sub][w] = p;
  }
  __syncthreads();

  // partials: S = sum_i ptw_i * hs2_i (W11 applied once in phase C)
  float pw = g_ptw[b * NN + i];
  pf[sub][h] = pw * hsm[sub][h];
  if (lt == 0) {
    float gam = red[sub][0] + red[sub][1] + b11g;
    float a2 = TWO_PI * gam;
    float co = cosf(a2), si = sinf(a2);
    pf[sub][64] = pw * (co * xi - si * yi);
    pf[sub][65] = pw * (si * xi + co * yi);
  }
  __syncthreads();

  if (t < 66) {
    float s = pf[0][t];
#pragma unroll
    for (int q = 1; q < IT2; ++q) s += pf[q][t];
    g_part[((size_t)b * 66 + t) * NB + bx] = s;
  }

  // ===================== Phase C: last block readout =====================
  __threadfence();
  if (t == 0) isLast = (atomicAdd(&g_cnt2[b], 1) == NB - 1);
  __syncthreads();
  if (!isLast) return;

  {
    int wid = t >> 5;  // 32 warps
    const float* part = g_part + (size_t)b * 66 * NB;
    for (int c = wid; c < 66; c += 32) {
      float v = (lane < NB) ? part[c * NB + lane] : 0.f;
#pragma unroll
      for (int o = 4; o; o >>= 1) v += __shfl_down_sync(0xffffffffu, v, o);
      if (lane == 0) gg[c] = v;
    }
    __syncthreads();

    // apply W11 once: gA = S @ W11[:, :64] + b11 (Σptw = 1)
    if (t < HH) {
      float z = b11[t];
#pragma unroll 8
      for (int k = 0; k < HH; ++k) z = fmaf(gg[k], W11[k * 65 + t], z);
      gA[t] = z;
    }
    __syncthreads();

    if (t < 32) {
      float z = br0[t];
#pragma unroll 8
      for (int d = 0; d < 64; ++d) z = fmaf(gA[d], Wr0[d * 32 + t], z);
      h1[t] = leaky(z);
    }
    __syncthreads();
    if (t < 32) {
      float z = br1[t];
#pragma unroll 8
      for (int d = 0; d < 32; ++d) z = fmaf(h1[d], Wr1[d * 32 + t], z);
      h2[t] = leaky(z);
    }
    __syncthreads();
    if (t == 0) {
      float z = br2[0];
#pragma unroll 8
      for (int d = 0; d < 32; ++d) z = fmaf(h2[d], Wr2[d], z);
      out[b * 3 + 0] = 1.f / (1.f + expf(-z));
      out[b * 3 + 1] = gg[64];
      out[b * 3 + 2] = gg[65];
      g_cnt1[b] = 0;   // reset for next graph replay
      g_cnt2[b] = 0;
    }
  }
}

extern "C" void kernel_launch(void* const* d_in, const int* in_sizes, int n_in,
                              void* d_out, int out_size) {
  const float* pt  = (const float*)d_in[0];
  const float* ang = (const float*)d_in[1];
  const float* W00 = (const float*)d_in[2];
  const float* b00 = (const float*)d_in[3];
  const float* W01 = (const float*)d_in[4];
  const float* b01 = (const float*)d_in[5];
  const float* W10 = (const float*)d_in[6];
  const float* b10 = (const float*)d_in[7];
  const float* W11 = (const float*)d_in[8];
  const float* b11 = (const float*)d_in[9];
  const float* Wr0 = (const float*)d_in[10];
  const float* br0 = (const float*)d_in[11];
  const float* Wr1 = (const float*)d_in[12];
  const float* br1 = (const float*)d_in[13];
  const float* Wr2 = (const float*)d_in[14];
  const float* br2 = (const float*)d_in[15];
  float* out = (float*)d_out;

  k_fused<<<dim3(NB, BB), NT>>>(ang, pt, W00, b00, W01, b01, W10, b10,
                                W11, b11, Wr0, br0, Wr1, br1, Wr2, br2, out);
}

// round 16
// speedup vs baseline: 1.1015x; 1.0890x over previous
#include <cuda_runtime.h>
#include <math.h>

#define BB 16
#define NN 128
#define HH 64
#define IT2 16         // i's per block
#define NB  (NN / IT2) // blocks per batch = 8
#define NT  1024
#define NEGS 0.01f
#define DRN2 0.16000000000000003f   // f32(0.4*0.4 in double)
#define TWO_PI 6.2831854820251465f  // 2.0 * np.float32(np.pi)

// Cross-block scratch
__device__ float g_a1[BB * NN * 2];
__device__ float g_v2[BB * NN * HH];
__device__ float g_ptw[BB * NN];
__device__ float g_part[BB * 66 * NB];
__device__ int   g_cnt1[BB];   // zero-init; reset by last block each run
__device__ int   g_cnt2[BB];

__device__ __forceinline__ float leaky(float z) {
  return fmaxf(z, 0.f) + NEGS * fminf(z, 0.f);
}

__global__ void __launch_bounds__(NT) k_fused(
    const float* __restrict__ ang, const float* __restrict__ pt,
    const float* __restrict__ W00, const float* __restrict__ b00,
    const float* __restrict__ W01, const float* __restrict__ b01,
    const float* __restrict__ W10, const float* __restrict__ b10,
    const float* __restrict__ W11, const float* __restrict__ b11,
    const float* __restrict__ Wr0, const float* __restrict__ br0,
    const float* __restrict__ Wr1, const float* __restrict__ br1,
    const float* __restrict__ Wr2, const float* __restrict__ br2,
    float* __restrict__ out) {
  int b = blockIdx.y;
  int bx = blockIdx.x;
  int t = threadIdx.x;
  int sub = t >> 6, lt = t & 63;
  int w = lt >> 5, lane = lt & 31;
  int i = bx * IT2 + sub;

  __shared__ float ax[NN], ay[NN], rr[NN];
  __shared__ unsigned msk[IT2][4];
  __shared__ float4 glist[IT2][NN];
  __shared__ float hsm[IT2][HH], fsm[IT2][HH];
  __shared__ float red[IT2][2];
  __shared__ float red4[4];
  __shared__ float big[2 * HH * HH];  // phase A: float2 (wua,wub); B: vsm
  __shared__ float pf[IT2][66];
  __shared__ float gg[66], gA[HH], h1[32], h2[32];
  __shared__ int isLast;

  // ===================== Phase A: layer 1 =====================
  // stage combined uv weights interleaved: wuv[d*HH+h] = (W10a-W10d, W10b+W10d)
  {
    float2* wuv = (float2*)big;
    for (int idx = t; idx < HH * HH; idx += NT) {
      float wa = W10[idx];
      float wb = W10[HH * HH + idx];
      float wd = W10[2 * HH * HH + idx];
      wuv[idx] = make_float2(wa - wd, wb + wd);
    }
  }
  if (t < NN) {
    float2 a = ((const float2*)ang)[b * NN + t];
    ax[t] = a.x; ay[t] = a.y;
    rr[t] = sqrtf(a.x * a.x + a.y * a.y);
  }
  float pv = 0.f;
  if (bx == 0 && t < NN) {
    pv = pt[b * NN + t];
    float s = pv;
    for (int o = 16; o; o >>= 1) s += __shfl_down_sync(0xffffffffu, s, o);
    if ((t & 31) == 0) red4[t >> 5] = s;
  }
  __syncthreads();
  if (bx == 0 && t < NN) {
    float invs = 1.f / (red4[0] + red4[1] + red4[2] + red4[3]);
    g_ptw[b * NN + t] = pv * invs;
  }

  int h = lt;
  // prefetch phase-B constants BEFORE the fence flushes L1
  float wc2 = W10[192 * HH + h], ws2 = W10[193 * HH + h];
  float w11g = W11[h * 65 + 64];
  float b11g = b11[64];

  float xi = ax[i], yi = ay[i];
  float r2i = xi * xi + yi * yi;

  {
    int j0 = lt, j1 = lt + 64;
    float x0 = ax[j0], y0 = ay[j0], x1 = ax[j1], y1 = ay[j1];
    float d0x = xi - x0, d0y = yi - y0, d1x = xi - x1, d1y = yi - y1;
    bool a0 = (d0x * d0x + d0y * d0y) <= DRN2;
    bool a1 = (d1x * d1x + d1y * d1y) <= DRN2;
    unsigned m0 = __ballot_sync(0xffffffffu, a0);
    unsigned m1 = __ballot_sync(0xffffffffu, a1);
    if (lane == 0) { msk[sub][w] = m0; msk[sub][2 + w] = m1; }
    __syncthreads();
    unsigned M0 = msk[sub][0], M1 = msk[sub][1], M2 = msk[sub][2], M3 = msk[sub][3];
    int c0 = __popc(M0), c1 = __popc(M1), c2 = __popc(M2);
    unsigned below = (1u << lane) - 1u;
    if (a0) {
      int base = (w == 0) ? 0 : c0;
      int pos = base + __popc((w == 0 ? M0 : M1) & below);
      float inv = rsqrtf(r2i * (x0 * x0 + y0 * y0));
      glist[sub][pos] = make_float4((xi * x0 + yi * y0) * inv,
                                    (yi * x0 - xi * y0) * inv, rr[j0], 0.f);
    }
    if (a1) {
      int base = c0 + c1 + ((w == 0) ? 0 : c2);
      int pos = base + __popc((w == 0 ? M2 : M3) & below);
      float inv = rsqrtf(r2i * (x1 * x1 + y1 * y1));
      glist[sub][pos] = make_float4((xi * x1 + yi * y1) * inv,
                                    (yi * x1 - xi * y1) * inv, rr[j1], 0.f);
    }
  }
  __syncthreads();

  {
    unsigned M0 = msk[sub][0], M1 = msk[sub][1], M2 = msk[sub][2], M3 = msk[sub][3];
    int deg = __popc(M0) + __popc(M1) + __popc(M2) + __popc(M3);
    float u  = fmaf(rr[i], W00[h] - W00[128 + h], b00[h]);
    float vc = W00[64 + h] + W00[128 + h];
    float wc = W00[192 + h], ws = W00[256 + h];
    float acc = 0.f;
    for (int q = 0; q < deg; ++q) {
      float4 g4 = glist[sub][q];
      float z = fmaf(g4.z, vc, u);
      z = fmaf(g4.x, wc, z);
      z = fmaf(g4.y, ws, z);
      acc += leaky(z);
    }
    hsm[sub][h] = acc * (1.f / (float)deg);
  }
  __syncthreads();

  // f1 dot and gamma shuffle overlap in one sync window
  {
    float d0 = b01[h], d1 = 0.f;
#pragma unroll 8
    for (int k = 0; k < HH; k += 2) {
      d0 = fmaf(hsm[sub][k], W01[k * 65 + h], d0);
      d1 = fmaf(hsm[sub][k + 1], W01[(k + 1) * 65 + h], d1);
    }
    fsm[sub][h] = d0 + d1;
  }
  {
    float p = hsm[sub][h] * W01[h * 65 + 64];
    for (int o = 16; o; o >>= 1) p += __shfl_down_sync(0xffffffffu, p, o);
    if (lane == 0) red[sub][w] = p;
  }
  __syncthreads();

  if (lt == 0) {
    float gam = red[sub][0] + red[sub][1] + b01[64];
    float a2 = TWO_PI * gam;
    float co = cosf(a2), si = sinf(a2);
    g_a1[(b * NN + i) * 2 + 0] = co * xi - si * yi;
    g_a1[(b * NN + i) * 2 + 1] = si * xi + co * yi;
  }

  // u2 (register) and v2 (global) via interleaved wuv, 4 FMA chains
  float ureg;
  {
    const float2* wuv = (const float2*)big;
    float u0 = b10[h], u1 = 0.f, v0 = 0.f, v1 = 0.f;
#pragma unroll 8
    for (int d = 0; d < HH; d += 2) {
      float f0 = fsm[sub][d];
      float f1v = fsm[sub][d + 1];
      float2 w0 = wuv[d * HH + h];
      float2 w1 = wuv[(d + 1) * HH + h];
      u0 = fmaf(f0, w0.x, u0);
      v0 = fmaf(f0, w0.y, v0);
      u1 = fmaf(f1v, w1.x, u1);
      v1 = fmaf(f1v, w1.y, v1);
    }
    ureg = u0 + u1;
    g_v2[(b * NN + i) * HH + h] = v0 + v1;
  }

  // ===================== Batch barrier =====================
  __syncthreads();
  __threadfence();
  if (t == 0) {
    atomicAdd(&g_cnt1[b], 1);
    while (atomicAdd(&g_cnt1[b], 0) < NB) __nanosleep(32);
  }
  __syncthreads();

  // ===================== Phase B: layer 2 =====================
  if (t < NN) {
    float2 a = ((const float2*)g_a1)[b * NN + t];
    ax[t] = a.x; ay[t] = a.y;
  }
  {
    const float4* vsrc = (const float4*)(g_v2 + (size_t)b * NN * HH);
#pragma unroll
    for (int idx = t; idx < NN * HH / 4; idx += NT)
      ((float4*)big)[idx] = vsrc[idx];
  }
  __syncthreads();

  xi = ax[i]; yi = ay[i];
  r2i = xi * xi + yi * yi;

  {
    int j0 = lt, j1 = lt + 64;
    float x0 = ax[j0], y0 = ay[j0], x1 = ax[j1], y1 = ay[j1];
    float d0x = xi - x0, d0y = yi - y0, d1x = xi - x1, d1y = yi - y1;
    bool a0 = (d0x * d0x + d0y * d0y) <= DRN2;
    bool a1 = (d1x * d1x + d1y * d1y) <= DRN2;
    unsigned m0 = __ballot_sync(0xffffffffu, a0);
    unsigned m1 = __ballot_sync(0xffffffffu, a1);
    if (lane == 0) { msk[sub][w] = m0; msk[sub][2 + w] = m1; }
    __syncthreads();
    unsigned M0 = msk[sub][0], M1 = msk[sub][1], M2 = msk[sub][2], M3 = msk[sub][3];
    int c0 = __popc(M0), c1 = __popc(M1), c2 = __popc(M2);
    unsigned below = (1u << lane) - 1u;
    if (a0) {
      int base = (w == 0) ? 0 : c0;
      int pos = base + __popc((w == 0 ? M0 : M1) & below);
      float inv = rsqrtf(r2i * (x0 * x0 + y0 * y0));
      glist[sub][pos] = make_float4((xi * x0 + yi * y0) * inv,
                                    (yi * x0 - xi * y0) * inv,
                                    __int_as_float(j0 * HH), 0.f);
    }
    if (a1) {
      int base = c0 + c1 + ((w == 0) ? 0 : c2);
      int pos = base + __popc((w == 0 ? M2 : M3) & below);
      float inv = rsqrtf(r2i * (x1 * x1 + y1 * y1));
      glist[sub][pos] = make_float4((xi * x1 + yi * y1) * inv,
                                    (yi * x1 - xi * y1) * inv,
                                    __int_as_float(j1 * HH), 0.f);
    }
  }
  __syncthreads();

  {
    unsigned M0 = msk[sub][0], M1 = msk[sub][1], M2 = msk[sub][2], M3 = msk[sub][3];
    int deg = __popc(M0) + __popc(M1) + __popc(M2) + __popc(M3);
    float acc = 0.f;
    for (int q = 0; q < deg; ++q) {
      float4 g4 = glist[sub][q];
      float z = ureg + big[__float_as_int(g4.z) + h];
      z = fmaf(g4.x, wc2, z);
      z = fmaf(g4.y, ws2, z);
      acc += leaky(z);
    }
    hsm[sub][h] = acc * (1.f / (float)deg);
  }

  {
    float p = hsm[sub][h] * w11g;
    for (int o = 16; o; o >>= 1) p += __shfl_down_sync(0xffffffffu, p, o);
    if (lane == 0) red[sub][w] = p;
  }
  __syncthreads();

  // partials: S = sum_i ptw_i * hs2_i (W11 applied once in phase C)
  float pw = g_ptw[b * NN + i];
  pf[sub][h] = pw * hsm[sub][h];
  if (lt == 0) {
    float gam = red[sub][0] + red[sub][1] + b11g;
    float a2 = TWO_PI * gam;
    float co = cosf(a2), si = sinf(a2);
    pf[sub][64] = pw * (co * xi - si * yi);
    pf[sub][65] = pw * (si * xi + co * yi);
  }
  __syncthreads();

  if (t < 66) {
    float s = pf[0][t];
#pragma unroll
    for (int q = 1; q < IT2; ++q) s += pf[q][t];
    g_part[((size_t)b * 66 + t) * NB + bx] = s;
  }

  // ===================== Phase C: last block readout =====================
  __threadfence();
  if (t == 0) isLast = (atomicAdd(&g_cnt2[b], 1) == NB - 1);
  __syncthreads();
  if (!isLast) return;

  {
    int wid = t >> 5;  // 32 warps
    const float* part = g_part + (size_t)b * 66 * NB;
    for (int c = wid; c < 66; c += 32) {
      float v = (lane < NB) ? part[c * NB + lane] : 0.f;
#pragma unroll
      for (int o = 4; o; o >>= 1) v += __shfl_down_sync(0xffffffffu, v, o);
      if (lane == 0) gg[c] = v;
    }
    __syncthreads();

    // apply W11 once: gA = S @ W11[:, :64] + b11 (Σptw = 1)
    if (t < HH) {
      float z = b11[t];
#pragma unroll 8
      for (int k = 0; k < HH; ++k) z = fmaf(gg[k], W11[k * 65 + t], z);
      gA[t] = z;
    }
    __syncthreads();

    if (t < 32) {
      float z = br0[t];
#pragma unroll 8
      for (int d = 0; d < 64; ++d) z = fmaf(gA[d], Wr0[d * 32 + t], z);
      h1[t] = leaky(z);
    }
    __syncthreads();
    if (t < 32) {
      float z = br1[t];
#pragma unroll 8
      for (int d = 0; d < 32; ++d) z = fmaf(h1[d], Wr1[d * 32 + t], z);
      h2[t] = leaky(z);
    }
    __syncthreads();
    if (t == 0) {
      float z = br2[0];
#pragma unroll 8
      for (int d = 0; d < 32; ++d) z = fmaf(h2[d], Wr2[d], z);
      out[b * 3 + 0] = 1.f / (1.f + expf(-z));
      out[b * 3 + 1] = gg[64];
      out[b * 3 + 2] = gg[65];
      g_cnt1[b] = 0;   // reset for next graph replay
      g_cnt2[b] = 0;
    }
  }
}

extern "C" void kernel_launch(void* const* d_in, const int* in_sizes, int n_in,
                              void* d_out, int out_size) {
  const float* pt  = (const float*)d_in[0];
  const float* ang = (const float*)d_in[1];
  const float* W00 = (const float*)d_in[2];
  const float* b00 = (const float*)d_in[3];
  const float* W01 = (const float*)d_in[4];
  const float* b01 = (const float*)d_in[5];
  const float* W10 = (const float*)d_in[6];
  const float* b10 = (const float*)d_in[7];
  const float* W11 = (const float*)d_in[8];
  const float* b11 = (const float*)d_in[9];
  const float* Wr0 = (const float*)d_in[10];
  const float* br0 = (const float*)d_in[11];
  const float* Wr1 = (const float*)d_in[12];
  const float* br1 = (const float*)d_in[13];
  const float* Wr2 = (const float*)d_in[14];
  const float* br2 = (const float*)d_in[15];
  float* out = (float*)d_out;

  k_fused<<<dim3(NB, BB), NT>>>(ang, pt, W00, b00, W01, b01, W10, b10,
                                W11, b11, Wr0, br0, Wr1, br1, Wr2, br2, out);
}